// round 9
// baseline (speedup 1.0000x reference)
#include <cuda_runtime.h>
#include <cstdint>
#include <math.h>

// Problem constants
#define BB 4
#define SS 4096
#define NN 4096
#define CC 32

#define KCH 128              // k (n) per staged chunk
#define NSTAGE (NN / KCH)    // 32
#define STILES (SS / 128)    // 32 s-tiles of 128 rows
#define NTHREADS 512         // 16 warps: 8 row-groups x 2 K-halves
#define XST 68               // xsh row stride in u32 (64 k-pairs + 4 pad; 68/4 odd)
#define XBUF (CC * XST)      // u32 per buffer (2176)

typedef unsigned long long ull;

// ---- packed f32x2 helpers ----
__device__ __forceinline__ ull pk2(float lo, float hi) {
    ull r; asm("mov.b64 %0, {%1, %2};" : "=l"(r) : "f"(lo), "f"(hi)); return r;
}
__device__ __forceinline__ float2 upk2(ull v) {
    float lo, hi; asm("mov.b64 {%0, %1}, %2;" : "=f"(lo), "=f"(hi) : "l"(v));
    return make_float2(lo, hi);
}
__device__ __forceinline__ ull fma2n(ull a, ull b, ull c) {
    ull r; asm("fma.rn.f32x2 %0, %1, %2, %3;" : "=l"(r) : "l"(a), "l"(b), "l"(c)); return r;
}
__device__ __forceinline__ ull mul2(ull a, ull b) {
    ull r; asm("mul.rn.f32x2 %0, %1, %2;" : "=l"(r) : "l"(a), "l"(b)); return r;
}
__device__ __forceinline__ ull add2(ull a, ull b) {
    ull r; asm("add.rn.f32x2 %0, %1, %2;" : "=l"(r) : "l"(a), "l"(b)); return r;
}
// pack two f32 -> f16x2 (RNE). lo = low half of result.
__device__ __forceinline__ uint32_t f2h2(float lo, float hi) {
    uint32_t r; asm("cvt.rn.f16x2.f32 %0, %1, %2;" : "=r"(r) : "f"(hi), "f"(lo)); return r;
}

// m16n8k16 fp16 HMMA, D(f32) += A(f16)*B(f16)
__device__ __forceinline__ void mma16(float d[4], const uint32_t a[4],
                                      uint32_t b0, uint32_t b1) {
    asm volatile(
        "mma.sync.aligned.m16n8k16.row.col.f32.f16.f16.f32 "
        "{%0,%1,%2,%3}, {%4,%5,%6,%7}, {%8,%9}, {%0,%1,%2,%3};"
        : "+f"(d[0]), "+f"(d[1]), "+f"(d[2]), "+f"(d[3])
        : "r"(a[0]), "r"(a[1]), "r"(a[2]), "r"(a[3]), "r"(b0), "r"(b1));
}

// ldmatrix x4: four 8x8 b16 matrices; thread t supplies row address
__device__ __forceinline__ void ldsm4(uint32_t& r0, uint32_t& r1,
                                      uint32_t& r2, uint32_t& r3, uint32_t addr) {
    asm volatile("ldmatrix.sync.aligned.m8n8.x4.shared.b16 {%0,%1,%2,%3}, [%4];"
        : "=r"(r0), "=r"(r1), "=r"(r2), "=r"(r3) : "r"(addr));
}

// Range reduction: phase = k*pi + r, |r| <= pi/2
#define INVPI    0.31830987334251403809f   /* fl(1/pi) */
#define PI_A     3.14159274101257324219f   /* fl(pi) */
#define PI_B     (-8.74227765734758577e-8f)/* pi - fl(pi) */
#define MAGIC    12582912.0f               /* 1.5 * 2^23 */
#define ROWK     (-1.5339807878856412e-3f) /* fl(-2*pi/4096) */

// cos(sqrt(q)) Taylor (even), residual ~2.6e-5 on [0,(pi/2)^2] — << fp16 ulp
#define CP8  2.48015873015873016e-5f
#define CP6  (-1.38888888888888889e-3f)
#define CP4  4.16666666666666667e-2f

// parity(k) sign mask for an f16x2 pair: lo k -> bit15, hi k -> bit31
__device__ __forceinline__ uint32_t parity_mask(ull m) {
    uint32_t lo = (uint32_t)m;
    uint32_t hi = (uint32_t)(m >> 32);
    return ((lo << 15) & 0x8000u) | (hi << 31);
}

__global__ __launch_bounds__(NTHREADS, 1)
void fudft_hmma(const float* __restrict__ x,
                const float* __restrict__ t,
                const float* __restrict__ freqs,
                float* __restrict__ out) {
    // cols_sm doubles as the K-half exchange buffer in the epilogue (16 KB)
    __shared__ __align__(16) float cols_sm[NN];
    // X^T chunk, double-buffered: [c][kpair] f16x2, row stride XST u32
    __shared__ __align__(16) uint32_t xsh[2 * XBUF];   // 17.4 KB

    const int tid  = threadIdx.x;
    const int wid  = tid >> 5;
    const int lane = tid & 31;
    const int wg   = wid & 7;       // row group 0..7 (16 rows each)
    const int kh   = wid >> 3;      // K-half 0/1
    const int g    = lane >> 2;     // 0..7
    const int qid  = lane & 3;      // 0..3

    const int bx    = blockIdx.x;   // 0..127
    const int stile = bx & (STILES - 1);
    const int b     = bx >> 5;

    // ---- stage cols for the whole batch row (once) ----
    {
        const float4* t4 = (const float4*)(t + (size_t)b * NN);
        float4* c4 = (float4*)cols_sm;
#pragma unroll
        for (int r = 0; r < NN / 4 / NTHREADS; ++r) {
            float4 v = t4[tid + NTHREADS * r];
            v.x *= 4095.0f; v.y *= 4095.0f; v.z *= 4095.0f; v.w *= 4095.0f;
            c4[tid + NTHREADS * r] = v;
        }
    }

    // ---- per-thread row frequencies (A-fragment rows g and g+8) ----
    const int s_base = stile * 128 + wg * 16;
    const float rs0 = (freqs[s_base + g]     * 4095.0f) * ROWK;
    const float rs1 = (freqs[s_base + g + 8] * 4095.0f) * ROWK;
    const ull rs0_2  = pk2(rs0, rs0);
    const ull rs1_2  = pk2(rs1, rs1);
    const ull invpi2 = pk2(INVPI, INVPI);
    const ull magic2 = pk2(MAGIC, MAGIC);
    const ull nmag2  = pk2(-MAGIC, -MAGIC);
    const ull nA2    = pk2(-PI_A, -PI_A);
    const ull nB2    = pk2(-PI_B, -PI_B);
    const ull cp8_2  = pk2(CP8, CP8);
    const ull cp6_2  = pk2(CP6, CP6);
    const ull cp4_2  = pk2(CP4, CP4);
    const ull nh2    = pk2(-0.5f, -0.5f);
    const ull one2   = pk2(1.0f, 1.0f);

    float dre[4][4], dim[4][4];
#pragma unroll
    for (int nt = 0; nt < 4; ++nt)
#pragma unroll
        for (int j = 0; j < 4; ++j) { dre[nt][j] = 0.0f; dim[nt][j] = 0.0f; }

    // ---- ldmatrix per-lane row addressing ----
    const uint32_t xsh_base = (uint32_t)__cvta_generic_to_shared(xsh);
    const int lm_m  = lane >> 3;
    const int lm_c  = 8 * (lm_m >> 1) + (lane & 7);
    const uint32_t lm_i0 = (uint32_t)(lm_c * XST + 4 * (lm_m & 1) + kh * 32);

    // ---- staging decomposition ----
    const float4* xg = (const float4*)(x + (size_t)b * NN * CC);
    const int kk   = tid >> 3;        // 0..63 (k row of v0; v1 is k+64)
    const int aa   = tid & 7;         // c block: c0 = 4*aa
    const int kodd = kk & 1;
    const int kp   = kk >> 1;         // k-pair col (v0); v1: +32
    const int c0   = aa * 4;

    // prefetch chunk 0
    float4 v0 = xg[tid];
    float4 v1 = xg[tid + NTHREADS];

    // stage chunk 0 into buffer 0
    {
        uint32_t* dst = xsh;
#pragma unroll
        for (int h = 0; h < 2; ++h) {
            const float4 v = h ? v1 : v0;
            const int col = kp + 32 * h;
            uint32_t q0 = f2h2(v.x, v.y);
            uint32_t q1 = f2h2(v.z, v.w);
            uint32_t s0 = __shfl_xor_sync(0xffffffffu, q0, 8);
            uint32_t s1 = __shfl_xor_sync(0xffffffffu, q1, 8);
            if (!kodd) {
                dst[c0 * XST + col]       = __byte_perm(q0, s0, 0x5410);
                dst[(c0 + 1) * XST + col] = __byte_perm(q0, s0, 0x7632);
            } else {
                dst[(c0 + 2) * XST + col] = __byte_perm(s1, q1, 0x5410);
                dst[(c0 + 3) * XST + col] = __byte_perm(s1, q1, 0x7632);
            }
        }
    }
    __syncthreads();

#pragma unroll 1
    for (int st = 0; st < NSTAGE; ++st) {
        const int p = st & 1;

        // prefetch next chunk early (regs held through compute)
        if (st < NSTAGE - 1) {
            v0 = xg[(st + 1) * 1024 + tid];
            v1 = xg[(st + 1) * 1024 + tid + NTHREADS];
        }

        const float* cols_loc = cols_sm + st * KCH;
        uint32_t aA = xsh_base + (uint32_t)((p ? XBUF : 0) + lm_i0) * 4u;
        uint32_t aB = aA + 16 * XST * 4;

        // this warp covers k16-steps kh*64 .. kh*64+63 within the 128-k chunk
#pragma unroll
        for (int ks2 = 0; ks2 < 4; ++ks2) {
            const int k0 = kh * 64 + ks2 * 16;
            const ull cA = *(const ull*)(cols_loc + k0 + 2 * qid);
            const ull cB = *(const ull*)(cols_loc + k0 + 2 * qid + 8);

            uint32_t ac[4], as_[4];
            // one vector = 2 angles: reduce mod pi, sin via MUFU, cos via poly
#pragma unroll
            for (int vv = 0; vv < 4; ++vv) {
                const ull rsv = (vv & 1) ? rs1_2 : rs0_2;
                const ull cv  = (vv & 2) ? cB : cA;
                ull ph = mul2(rsv, cv);
                ull m  = fma2n(ph, invpi2, magic2);
                ull kf = add2(m, nmag2);
                ull r  = fma2n(kf, nA2, ph);
                r      = fma2n(kf, nB2, r);
                ull q  = mul2(r, r);
                ull pc = fma2n(q, cp8_2, cp6_2);
                pc     = fma2n(q, pc, cp4_2);
                pc     = fma2n(q, pc, nh2);
                pc     = fma2n(q, pc, one2);
                const float2 rr = upk2(r);
                const float2 cc = upk2(pc);
                const uint32_t msk = parity_mask(m);
                ac[vv]  = f2h2(cc.x, cc.y) ^ msk;
                as_[vv] = f2h2(__sinf(rr.x), __sinf(rr.y)) ^ msk;
            }
            // reorder to fragment convention: a[1] <-> rows g+8 (rs1)
            // vv mapping: 0=(rs0,cA) 1=(rs1,cA) 2=(rs0,cB) 3=(rs1,cB)
            // fragment wants: [ (rs0,cA), (rs1,cA), (rs0,cB), (rs1,cB) ] - already matches

            // B fragments: 2 x ldmatrix.x4 = b0,b1 for nt=0..3
            uint32_t bq[8];
            ldsm4(bq[0], bq[1], bq[2], bq[3], aA);
            ldsm4(bq[4], bq[5], bq[6], bq[7], aB);
            aA += 32; aB += 32;     // +8 u32 = next k16 step

#pragma unroll
            for (int nt = 0; nt < 4; ++nt) {
                mma16(dre[nt], ac,  bq[2 * nt], bq[2 * nt + 1]);
                mma16(dim[nt], as_, bq[2 * nt], bq[2 * nt + 1]);
            }
        }

        // stage next chunk into the other buffer (overlaps other warps' compute)
        if (st < NSTAGE - 1) {
            uint32_t* dst = xsh + (p ? 0 : XBUF);
#pragma unroll
            for (int h = 0; h < 2; ++h) {
                const float4 v = h ? v1 : v0;
                const int col = kp + 32 * h;
                uint32_t q0 = f2h2(v.x, v.y);
                uint32_t q1 = f2h2(v.z, v.w);
                uint32_t s0 = __shfl_xor_sync(0xffffffffu, q0, 8);
                uint32_t s1 = __shfl_xor_sync(0xffffffffu, q1, 8);
                if (!kodd) {
                    dst[c0 * XST + col]       = __byte_perm(q0, s0, 0x5410);
                    dst[(c0 + 1) * XST + col] = __byte_perm(q0, s0, 0x7632);
                } else {
                    dst[(c0 + 2) * XST + col] = __byte_perm(s1, q1, 0x5410);
                    dst[(c0 + 3) * XST + col] = __byte_perm(s1, q1, 0x7632);
                }
            }
        }
        __syncthreads();
    }

    // ---- merge K-halves through cols_sm in 2 phases (nt pair per phase) ----
    const int s0g = s_base + g;
    const int s1g = s0g + 8;
    const bool z0 = (s0g == 0) || (s0g == SS - 1);
    const bool z1 = (s1g == 0) || (s1g == SS - 1);
    float* o0 = out + ((size_t)b * SS + s0g) * CC;
    float* o1 = out + ((size_t)b * SS + s1g) * CC;

#pragma unroll
    for (int p = 0; p < 2; ++p) {
        if (kh == 1) {
            float4* ex = (float4*)cols_sm;
#pragma unroll
            for (int j = 0; j < 2; ++j) {
                const int nt = 2 * p + j;
                ex[(wg * 4 + j * 2)     * 32 + lane] = *(const float4*)dre[nt];
                ex[(wg * 4 + j * 2 + 1) * 32 + lane] = *(const float4*)dim[nt];
            }
        }
        __syncthreads();
        if (kh == 0) {
            const float4* ex = (const float4*)cols_sm;
#pragma unroll
            for (int j = 0; j < 2; ++j) {
                const int nt = 2 * p + j;
                float4 hre = ex[(wg * 4 + j * 2)     * 32 + lane];
                float4 him = ex[(wg * 4 + j * 2 + 1) * 32 + lane];
                float re0 = dre[nt][0] + hre.x, im0 = dim[nt][0] + him.x;
                float re1 = dre[nt][1] + hre.y, im1 = dim[nt][1] + him.y;
                float re2 = dre[nt][2] + hre.z, im2 = dim[nt][2] + him.z;
                float re3 = dre[nt][3] + hre.w, im3 = dim[nt][3] + him.w;
                const int c = nt * 8 + 2 * qid;
                float2 w;
                w.x = z0 ? 0.0f : sqrtf(fmaf(re0, re0, im0 * im0)) * 0.015625f;
                w.y = z0 ? 0.0f : sqrtf(fmaf(re1, re1, im1 * im1)) * 0.015625f;
                *(float2*)(o0 + c) = w;
                w.x = z1 ? 0.0f : sqrtf(fmaf(re2, re2, im2 * im2)) * 0.015625f;
                w.y = z1 ? 0.0f : sqrtf(fmaf(re3, re3, im3 * im3)) * 0.015625f;
                *(float2*)(o1 + c) = w;
            }
        }
        if (p == 0) __syncthreads();
    }
}

extern "C" void kernel_launch(void* const* d_in, const int* in_sizes, int n_in,
                              void* d_out, int out_size) {
    const float* x     = (const float*)d_in[0];   // [4,4096,32]
    const float* t     = (const float*)d_in[1];   // [4,4096]
    const float* freqs = (const float*)d_in[2];   // [4096]
    float* out = (float*)d_out;                   // [4,4096,32]

    fudft_hmma<<<BB * STILES, NTHREADS>>>(x, t, freqs, out);
}

// round 10
// speedup vs baseline: 1.1385x; 1.1385x over previous
#include <cuda_runtime.h>
#include <cstdint>
#include <math.h>

// Problem constants
#define BB 4
#define SS 4096
#define NN 4096
#define CC 32

#define KCH 64               // k (n) per staged chunk (per half-CTA)
#define NCH 32               // chunks per half (covers 2048 n each)
#define STILES (SS / 128)    // 32 s-tiles of 128 rows
#define NTHREADS 512         // 16 warps: 2 half-CTAs x 8 row-group warps
#define XST 36               // xsh row stride in u32 (32 k-pairs + 4 pad; 36/4 odd)
#define XBUF (CC * XST)      // u32 per buffer (1152)

typedef unsigned long long ull;

// ---- packed f32x2 helpers ----
__device__ __forceinline__ ull pk2(float lo, float hi) {
    ull r; asm("mov.b64 %0, {%1, %2};" : "=l"(r) : "f"(lo), "f"(hi)); return r;
}
__device__ __forceinline__ float2 upk2(ull v) {
    float lo, hi; asm("mov.b64 {%0, %1}, %2;" : "=f"(lo), "=f"(hi) : "l"(v));
    return make_float2(lo, hi);
}
__device__ __forceinline__ ull fma2n(ull a, ull b, ull c) {
    ull r; asm("fma.rn.f32x2 %0, %1, %2, %3;" : "=l"(r) : "l"(a), "l"(b), "l"(c)); return r;
}
__device__ __forceinline__ ull mul2(ull a, ull b) {
    ull r; asm("mul.rn.f32x2 %0, %1, %2;" : "=l"(r) : "l"(a), "l"(b)); return r;
}
__device__ __forceinline__ ull add2(ull a, ull b) {
    ull r; asm("add.rn.f32x2 %0, %1, %2;" : "=l"(r) : "l"(a), "l"(b)); return r;
}
// pack two f32 -> f16x2 (RNE). lo = low half of result.
__device__ __forceinline__ uint32_t f2h2(float lo, float hi) {
    uint32_t r; asm("cvt.rn.f16x2.f32 %0, %1, %2;" : "=r"(r) : "f"(hi), "f"(lo)); return r;
}

// m16n8k16 fp16 HMMA, D(f32) += A(f16)*B(f16)
__device__ __forceinline__ void mma16(float d[4], const uint32_t a[4],
                                      uint32_t b0, uint32_t b1) {
    asm volatile(
        "mma.sync.aligned.m16n8k16.row.col.f32.f16.f16.f32 "
        "{%0,%1,%2,%3}, {%4,%5,%6,%7}, {%8,%9}, {%0,%1,%2,%3};"
        : "+f"(d[0]), "+f"(d[1]), "+f"(d[2]), "+f"(d[3])
        : "r"(a[0]), "r"(a[1]), "r"(a[2]), "r"(a[3]), "r"(b0), "r"(b1));
}

// ldmatrix x4: four 8x8 b16 matrices; thread t supplies row address
__device__ __forceinline__ void ldsm4(uint32_t& r0, uint32_t& r1,
                                      uint32_t& r2, uint32_t& r3, uint32_t addr) {
    asm volatile("ldmatrix.sync.aligned.m8n8.x4.shared.b16 {%0,%1,%2,%3}, [%4];"
        : "=r"(r0), "=r"(r1), "=r"(r2), "=r"(r3) : "r"(addr));
}

// half-CTA barrier: named barrier (1+kh), 256 threads
__device__ __forceinline__ void half_bar(int kh) {
    asm volatile("bar.sync %0, %1;" :: "r"(1 + kh), "r"(256) : "memory");
}

// Range reduction: phase = k*2pi + r, |r| <= pi
#define INV2PI   0.15915493667125701904f
#define TWOPI_A  6.28318548202514648438f
#define TWOPI_B  (-1.74845552749343265e-7f)
#define MAGIC    12582912.0f    /* 1.5 * 2^23 */
#define ROWK     (-1.5339807878856412e-3f)   /* fl(-2*pi/4096) */

__global__ __launch_bounds__(NTHREADS, 1)
void fudft_hmma(const float* __restrict__ x,
                const float* __restrict__ t,
                const float* __restrict__ freqs,
                float* __restrict__ out) {
    // cols_sm doubles as the K-half exchange buffer in the epilogue (16 KB)
    __shared__ __align__(16) float cols_sm[NN];
    // per-half, double-buffered X^T chunk: [half][buf][c][kpair] f16x2
    __shared__ __align__(16) uint32_t xsh[2 * 2 * XBUF];   // 18.4 KB

    const int tid  = threadIdx.x;
    const int wid  = tid >> 5;
    const int lane = tid & 31;
    const int wg   = wid & 7;       // row group 0..7 (16 rows each)
    const int kh   = wid >> 3;      // half-CTA id (n-range split)
    const int g    = lane >> 2;     // 0..7
    const int qid  = lane & 3;      // 0..3
    const int htid = tid & 255;     // thread id within half

    const int bx    = blockIdx.x;   // 0..127
    const int stile = bx & (STILES - 1);
    const int b     = bx >> 5;

    // ---- stage cols for the whole batch row (once, all 512 threads) ----
    {
        const float4* t4 = (const float4*)(t + (size_t)b * NN);
        float4* c4 = (float4*)cols_sm;
#pragma unroll
        for (int r = 0; r < NN / 4 / NTHREADS; ++r) {
            float4 v = t4[tid + NTHREADS * r];
            v.x *= 4095.0f; v.y *= 4095.0f; v.z *= 4095.0f; v.w *= 4095.0f;
            c4[tid + NTHREADS * r] = v;
        }
    }

    // ---- per-thread row frequencies (A-fragment rows g and g+8) ----
    const int s_base = stile * 128 + wg * 16;
    const float rs0 = (freqs[s_base + g]     * 4095.0f) * ROWK;
    const float rs1 = (freqs[s_base + g + 8] * 4095.0f) * ROWK;
    const ull rs0_2   = pk2(rs0, rs0);
    const ull rs1_2   = pk2(rs1, rs1);
    const ull inv2pi2 = pk2(INV2PI, INV2PI);
    const ull magic2  = pk2(MAGIC, MAGIC);
    const ull nmag2   = pk2(-MAGIC, -MAGIC);
    const ull nA2     = pk2(-TWOPI_A, -TWOPI_A);
    const ull nB2     = pk2(-TWOPI_B, -TWOPI_B);

    float dre[4][4], dim[4][4];
#pragma unroll
    for (int nt = 0; nt < 4; ++nt)
#pragma unroll
        for (int j = 0; j < 4; ++j) { dre[nt][j] = 0.0f; dim[nt][j] = 0.0f; }

    // ---- ldmatrix per-lane row addressing (within this half's buffers) ----
    const uint32_t xsh_base = (uint32_t)__cvta_generic_to_shared(xsh)
                            + (uint32_t)(kh * 2 * XBUF) * 4u;
    const int lm_m  = lane >> 3;
    const int lm_c  = 8 * (lm_m >> 1) + (lane & 7);
    const uint32_t lm_i0 = (uint32_t)(lm_c * XST + 4 * (lm_m & 1));

    // ---- staging decomposition (per half: 64k x 32c per chunk) ----
    const int base_n = kh * 2048;                   // this half's n range
    const float4* xg = (const float4*)(x + (size_t)b * NN * CC);
    const int kk   = htid >> 3;       // 0..31 (k row of v0; v1 is k+32)
    const int aa   = htid & 7;        // c block: c0 = 4*aa
    const int kodd = kk & 1;
    const int kp   = kk >> 1;         // k-pair col (v0: +0, v1: +16)
    const int c0   = aa * 4;
    uint32_t* const myxsh = xsh + kh * 2 * XBUF;

    __syncthreads();   // cols ready (full CTA, once)

    // prefetch chunk 0 of this half (64k*32c = 512 float4; 2 per thread)
    float4 v0 = xg[base_n * 8 + htid];
    float4 v1 = xg[base_n * 8 + htid + 256];

    // stage chunk 0 into buffer 0
    {
        uint32_t* dst = myxsh;
#pragma unroll
        for (int h = 0; h < 2; ++h) {
            const float4 v = h ? v1 : v0;
            const int col = kp + 16 * h;
            uint32_t q0 = f2h2(v.x, v.y);
            uint32_t q1 = f2h2(v.z, v.w);
            uint32_t s0 = __shfl_xor_sync(0xffffffffu, q0, 8);
            uint32_t s1 = __shfl_xor_sync(0xffffffffu, q1, 8);
            if (!kodd) {
                dst[c0 * XST + col]       = __byte_perm(q0, s0, 0x5410);
                dst[(c0 + 1) * XST + col] = __byte_perm(q0, s0, 0x7632);
            } else {
                dst[(c0 + 2) * XST + col] = __byte_perm(s1, q1, 0x5410);
                dst[(c0 + 3) * XST + col] = __byte_perm(s1, q1, 0x7632);
            }
        }
    }
    half_bar(kh);

#pragma unroll 1
    for (int st = 0; st < NCH; ++st) {
        const int p = st & 1;
        const int n0 = base_n + st * KCH;

        // prefetch next chunk early (regs held through compute)
        if (st < NCH - 1) {
            v0 = xg[(n0 + KCH) * 8 + htid];
            v1 = xg[(n0 + KCH) * 8 + htid + 256];
        }

        const float* cols_loc = cols_sm + n0;
        uint32_t aA = xsh_base + (uint32_t)(p * XBUF + lm_i0) * 4u;
        uint32_t aB = aA + 16 * XST * 4;

        // 4 k16-steps over this 64-k chunk
#pragma unroll
        for (int ks2 = 0; ks2 < 4; ++ks2) {
            const int k0 = ks2 * 16;

            // B fragments first: LDS latency hides under MUFU below
            uint32_t bq[8];
            ldsm4(bq[0], bq[1], bq[2], bq[3], aA);
            ldsm4(bq[4], bq[5], bq[6], bq[7], aB);
            aA += 32; aB += 32;     // +8 u32 = next k16 step

            const ull cA = *(const ull*)(cols_loc + k0 + 2 * qid);
            const ull cB = *(const ull*)(cols_loc + k0 + 2 * qid + 8);

            ull p00 = mul2(rs0_2, cA), p01 = mul2(rs0_2, cB);
            ull p10 = mul2(rs1_2, cA), p11 = mul2(rs1_2, cB);
            ull m00 = fma2n(p00, inv2pi2, magic2), m01 = fma2n(p01, inv2pi2, magic2);
            ull m10 = fma2n(p10, inv2pi2, magic2), m11 = fma2n(p11, inv2pi2, magic2);
            ull k00 = add2(m00, nmag2), k01 = add2(m01, nmag2);
            ull k10 = add2(m10, nmag2), k11 = add2(m11, nmag2);
            ull r00 = fma2n(k00, nA2, p00); r00 = fma2n(k00, nB2, r00);
            ull r01 = fma2n(k01, nA2, p01); r01 = fma2n(k01, nB2, r01);
            ull r10 = fma2n(k10, nA2, p10); r10 = fma2n(k10, nB2, r10);
            ull r11 = fma2n(k11, nA2, p11); r11 = fma2n(k11, nB2, r11);
            const float2 f00 = upk2(r00), f01 = upk2(r01);
            const float2 f10 = upk2(r10), f11 = upk2(r11);

            uint32_t ac[4], as_[4];
            ac[0]  = f2h2(__cosf(f00.x), __cosf(f00.y));
            as_[0] = f2h2(__sinf(f00.x), __sinf(f00.y));
            ac[1]  = f2h2(__cosf(f10.x), __cosf(f10.y));
            as_[1] = f2h2(__sinf(f10.x), __sinf(f10.y));
            ac[2]  = f2h2(__cosf(f01.x), __cosf(f01.y));
            as_[2] = f2h2(__sinf(f01.x), __sinf(f01.y));
            ac[3]  = f2h2(__cosf(f11.x), __cosf(f11.y));
            as_[3] = f2h2(__sinf(f11.x), __sinf(f11.y));

#pragma unroll
            for (int nt = 0; nt < 4; ++nt) {
                mma16(dre[nt], ac,  bq[2 * nt], bq[2 * nt + 1]);
                mma16(dim[nt], as_, bq[2 * nt], bq[2 * nt + 1]);
            }
        }

        // stage next chunk into the other buffer
        if (st < NCH - 1) {
            uint32_t* dst = myxsh + (p ? 0 : XBUF);
#pragma unroll
            for (int h = 0; h < 2; ++h) {
                const float4 v = h ? v1 : v0;
                const int col = kp + 16 * h;
                uint32_t q0 = f2h2(v.x, v.y);
                uint32_t q1 = f2h2(v.z, v.w);
                uint32_t s0 = __shfl_xor_sync(0xffffffffu, q0, 8);
                uint32_t s1 = __shfl_xor_sync(0xffffffffu, q1, 8);
                if (!kodd) {
                    dst[c0 * XST + col]       = __byte_perm(q0, s0, 0x5410);
                    dst[(c0 + 1) * XST + col] = __byte_perm(q0, s0, 0x7632);
                } else {
                    dst[(c0 + 2) * XST + col] = __byte_perm(s1, q1, 0x5410);
                    dst[(c0 + 3) * XST + col] = __byte_perm(s1, q1, 0x7632);
                }
            }
        }
        half_bar(kh);
    }

    // ---- merge halves through cols_sm in 2 phases (nt pair per phase) ----
    __syncthreads();   // both halves done
    const int s0g = s_base + g;
    const int s1g = s0g + 8;
    const bool z0 = (s0g == 0) || (s0g == SS - 1);
    const bool z1 = (s1g == 0) || (s1g == SS - 1);
    float* o0 = out + ((size_t)b * SS + s0g) * CC;
    float* o1 = out + ((size_t)b * SS + s1g) * CC;

#pragma unroll
    for (int p = 0; p < 2; ++p) {
        if (kh == 1) {
            float4* ex = (float4*)cols_sm;
#pragma unroll
            for (int j = 0; j < 2; ++j) {
                const int nt = 2 * p + j;
                ex[(wg * 4 + j * 2)     * 32 + lane] = *(const float4*)dre[nt];
                ex[(wg * 4 + j * 2 + 1) * 32 + lane] = *(const float4*)dim[nt];
            }
        }
        __syncthreads();
        if (kh == 0) {
            const float4* ex = (const float4*)cols_sm;
#pragma unroll
            for (int j = 0; j < 2; ++j) {
                const int nt = 2 * p + j;
                float4 hre = ex[(wg * 4 + j * 2)     * 32 + lane];
                float4 him = ex[(wg * 4 + j * 2 + 1) * 32 + lane];
                float re0 = dre[nt][0] + hre.x, im0 = dim[nt][0] + him.x;
                float re1 = dre[nt][1] + hre.y, im1 = dim[nt][1] + him.y;
                float re2 = dre[nt][2] + hre.z, im2 = dim[nt][2] + him.z;
                float re3 = dre[nt][3] + hre.w, im3 = dim[nt][3] + him.w;
                const int c = nt * 8 + 2 * qid;
                float2 w;
                w.x = z0 ? 0.0f : sqrtf(fmaf(re0, re0, im0 * im0)) * 0.015625f;
                w.y = z0 ? 0.0f : sqrtf(fmaf(re1, re1, im1 * im1)) * 0.015625f;
                *(float2*)(o0 + c) = w;
                w.x = z1 ? 0.0f : sqrtf(fmaf(re2, re2, im2 * im2)) * 0.015625f;
                w.y = z1 ? 0.0f : sqrtf(fmaf(re3, re3, im3 * im3)) * 0.015625f;
                *(float2*)(o1 + c) = w;
            }
        }
        if (p == 0) __syncthreads();
    }
}

extern "C" void kernel_launch(void* const* d_in, const int* in_sizes, int n_in,
                              void* d_out, int out_size) {
    const float* x     = (const float*)d_in[0];   // [4,4096,32]
    const float* t     = (const float*)d_in[1];   // [4,4096]
    const float* freqs = (const float*)d_in[2];   // [4096]
    float* out = (float*)d_out;                   // [4,4096,32]

    fudft_hmma<<<BB * STILES, NTHREADS>>>(x, t, freqs, out);
}